// round 3
// baseline (speedup 1.0000x reference)
#include <cuda_runtime.h>

#define NN 8192
#define D 64
#define DO 128
#define K 16
#define SEG 8
#define JSEG (NN/SEG)       // 1024 j per block
#define TI 128
#define TJ 64
#define NTILES (JSEG/TJ)    // 16

// Scratch (no allocs allowed)
__device__ float g_sq[NN];
__device__ float g_p[NN * DO];
__device__ float g_q[NN * DO];
__device__ unsigned long long g_ck[NN * SEG * K];

// Packed fp32x2 FMA (Blackwell FFMA2 — PTX-only path)
__device__ __forceinline__ unsigned long long ffma2(unsigned long long a,
                                                    unsigned long long b,
                                                    unsigned long long c) {
    unsigned long long d;
    asm("fma.rn.f32x2 %0, %1, %2, %3;" : "=l"(d) : "l"(a), "l"(b), "l"(c));
    return d;
}

// ---------------------------------------------------------------------------
// Kernel 1: per-row squared norms + p = x@(W1a-W1b)+b1, q = x@W1b
// ---------------------------------------------------------------------------
__global__ __launch_bounds__(256) void pq_kernel(const float* __restrict__ x,
                                                 const float* __restrict__ W1,
                                                 const float* __restrict__ b1) {
    __shared__ float sx[8 * D];
    const int i0 = blockIdx.x * 8;
    const int t = threadIdx.x;

    for (int u = t; u < 8 * D; u += 256) sx[u] = x[i0 * D + u];
    __syncthreads();

    if (t < 8) {
        float s = 0.f;
        #pragma unroll
        for (int d = 0; d < D; d++) { float v = sx[t * D + d]; s = fmaf(v, v, s); }
        g_sq[i0 + t] = s;
    }

    float acc[8];
    #pragma unroll
    for (int m = 0; m < 8; m++) acc[m] = 0.f;

    if (t < DO) {
        const int c = t;
        for (int d = 0; d < D; d++) {
            float w = W1[d * DO + c] - W1[(D + d) * DO + c];
            #pragma unroll
            for (int m = 0; m < 8; m++) acc[m] = fmaf(sx[m * D + d], w, acc[m]);
        }
        float bb = b1[c];
        #pragma unroll
        for (int m = 0; m < 8; m++) g_p[(size_t)(i0 + m) * DO + c] = acc[m] + bb;
    } else {
        const int c = t - DO;
        for (int d = 0; d < D; d++) {
            float w = W1[(D + d) * DO + c];
            #pragma unroll
            for (int m = 0; m < 8; m++) acc[m] = fmaf(sx[m * D + d], w, acc[m]);
        }
        #pragma unroll
        for (int m = 0; m < 8; m++) g_q[(size_t)(i0 + m) * DO + c] = acc[m];
    }
}

// ---------------------------------------------------------------------------
// Kernel 2: kNN as register-tiled GEMM + fused per-row top-k scan.
// grid = (NN/TI, SEG), block = 128 threads.
// Each block: 128 i-rows vs JSEG j's in TJ=64 tiles. Microtile 8i x 8j per
// thread, FFMA2 over d-pairs. Dist tile staged j-major in smem; thread t
// scans row t keeping a sorted top-16 in registers.
// ---------------------------------------------------------------------------
struct KnnSmem {
    unsigned long long a2[32][130];  // [d-pair][i], pad keeps 16B align, 33280B
    unsigned long long b2[32][64];   // [d-pair][j], 16384B
    float dist[TJ][TI];              // j-major, scan is conflict-free, 32768B
    float sqi[TI];
    float sqj[TJ];
};
#define KNN_SMEM_BYTES sizeof(KnnSmem)

__global__ __launch_bounds__(128, 2) void knn_kernel(const float* __restrict__ x) {
    extern __shared__ char smraw[];
    KnnSmem& sm = *reinterpret_cast<KnnSmem*>(smraw);
    const int t = threadIdx.x;
    const int ib = blockIdx.x * TI;
    const int s = blockIdx.y;
    const int tx = t & 7;        // j-group: 8 groups x 8 j
    const int ty = t >> 3;       // i-group: 16 groups x 8 i

    const float2* x2 = reinterpret_cast<const float2*>(x);

    // Stage A tile once: x[ib..ib+127][*] transposed to d-pair-major.
    #pragma unroll
    for (int u = t; u < TI * 32; u += 128) {
        int dp = u & 31, i = u >> 5;
        float2 v = x2[(size_t)(ib + i) * 32 + dp];
        *reinterpret_cast<float2*>(&sm.a2[dp][i]) = v;
    }
    if (t < TI) sm.sqi[t] = g_sq[ib + t];

    float kd[K];
    int   kj[K];
    #pragma unroll
    for (int n = 0; n < K; n++) { kd[n] = 3.4e38f; kj[n] = 0; }

    for (int tile = 0; tile < NTILES; tile++) {
        const int jb = s * JSEG + tile * TJ;

        // Stage B tile (transposed, d-pair-major).
        #pragma unroll
        for (int u = t; u < TJ * 32; u += 128) {
            int dp = u & 31, j = u >> 5;
            float2 v = x2[(size_t)(jb + j) * 32 + dp];
            *reinterpret_cast<float2*>(&sm.b2[dp][j]) = v;
        }
        if (t < TJ) sm.sqj[t] = g_sq[jb + t];
        __syncthreads();   // B ready; also: everyone's previous scan done

        // GEMM: 8i x 8j microtile, f32x2 packed over d.
        unsigned long long acc[8][8];
        #pragma unroll
        for (int i = 0; i < 8; i++)
            #pragma unroll
            for (int j = 0; j < 8; j++) acc[i][j] = 0ull;

        #pragma unroll 4
        for (int dp = 0; dp < 32; dp++) {
            ulonglong2 a01 = *reinterpret_cast<const ulonglong2*>(&sm.a2[dp][ty * 8 + 0]);
            ulonglong2 a23 = *reinterpret_cast<const ulonglong2*>(&sm.a2[dp][ty * 8 + 2]);
            ulonglong2 a45 = *reinterpret_cast<const ulonglong2*>(&sm.a2[dp][ty * 8 + 4]);
            ulonglong2 a67 = *reinterpret_cast<const ulonglong2*>(&sm.a2[dp][ty * 8 + 6]);
            ulonglong2 b01 = *reinterpret_cast<const ulonglong2*>(&sm.b2[dp][tx * 8 + 0]);
            ulonglong2 b23 = *reinterpret_cast<const ulonglong2*>(&sm.b2[dp][tx * 8 + 2]);
            ulonglong2 b45 = *reinterpret_cast<const ulonglong2*>(&sm.b2[dp][tx * 8 + 4]);
            ulonglong2 b67 = *reinterpret_cast<const ulonglong2*>(&sm.b2[dp][tx * 8 + 6]);
            unsigned long long af[8] = {a01.x, a01.y, a23.x, a23.y, a45.x, a45.y, a67.x, a67.y};
            unsigned long long bf[8] = {b01.x, b01.y, b23.x, b23.y, b45.x, b45.y, b67.x, b67.y};
            #pragma unroll
            for (int i = 0; i < 8; i++)
                #pragma unroll
                for (int j = 0; j < 8; j++)
                    acc[i][j] = ffma2(af[i], bf[j], acc[i][j]);
        }

        // Epilogue: dist = sq_i + sq_j - 2*dot  ->  smem dist tile (j-major).
        #pragma unroll
        for (int i = 0; i < 8; i++) {
            float si = sm.sqi[ty * 8 + i];
            #pragma unroll
            for (int j = 0; j < 8; j++) {
                unsigned lo, hi;
                asm("mov.b64 {%0, %1}, %2;" : "=r"(lo), "=r"(hi) : "l"(acc[i][j]));
                float dot = __uint_as_float(lo) + __uint_as_float(hi);
                sm.dist[tx * 8 + j][ty * 8 + i] =
                    fmaf(-2.f, dot, si + sm.sqj[tx * 8 + j]);
            }
        }
        __syncthreads();   // dist tile ready

        // Scan: thread t owns row t, sorted top-16 insert.
        #pragma unroll 4
        for (int jj = 0; jj < TJ; jj++) {
            float dv = sm.dist[jj][t];
            if (dv < kd[K - 1]) {
                kd[K - 1] = dv; kj[K - 1] = jb + jj;
                #pragma unroll
                for (int n = K - 1; n > 0; n--) {
                    if (kd[n] < kd[n - 1]) {
                        float td = kd[n]; kd[n] = kd[n - 1]; kd[n - 1] = td;
                        int   tj = kj[n]; kj[n] = kj[n - 1]; kj[n - 1] = tj;
                    }
                }
            }
        }
    }

    // Writeout: total-order u64 keys, sorted ascending already.
    unsigned long long* dst = g_ck + ((size_t)(ib + t) * SEG + s) * K;
    #pragma unroll
    for (int n = 0; n < K; n++) {
        unsigned u = __float_as_uint(kd[n]);
        u = (u & 0x80000000u) ? ~u : (u | 0x80000000u);
        dst[n] = ((unsigned long long)u << 32) | (unsigned)kj[n];
    }
}

// ---------------------------------------------------------------------------
// Kernel 3: merge SEG x 16 candidates per row, aggregate, apply W2.
// ---------------------------------------------------------------------------
__global__ __launch_bounds__(128) void agg_kernel(const float* __restrict__ W2,
                                                  const float* __restrict__ b2,
                                                  float* __restrict__ out) {
    __shared__ unsigned long long skey[SEG * K];
    __shared__ int snbr[K];
    __shared__ float sr[DO];
    const int i = blockIdx.x;
    const int t = threadIdx.x;

    skey[t] = g_ck[(size_t)i * SEG * K + t];
    __syncthreads();
    {
        unsigned long long mk = skey[t];
        int rank = 0;
        #pragma unroll 4
        for (int u = 0; u < SEG * K; u++) rank += (skey[u] < mk);
        if (rank < K) snbr[rank] = (int)(mk & 0xFFFFFFFFull);
    }
    __syncthreads();

    float p = g_p[(size_t)i * DO + t];
    float acc = 0.f;
    #pragma unroll
    for (int n = 0; n < K; n++) {
        int j = snbr[n];
        acc += fmaxf(p + g_q[(size_t)j * DO + t], 0.f);
    }
    sr[t] = acc * (1.f / K);
    __syncthreads();

    float o = b2[t];
    #pragma unroll 8
    for (int d = 0; d < DO; d++)
        o = fmaf(sr[d], W2[d * DO + t], o);
    out[(size_t)i * DO + t] = o;
}

// ---------------------------------------------------------------------------
extern "C" void kernel_launch(void* const* d_in, const int* in_sizes, int n_in,
                              void* d_out, int out_size) {
    const float* x  = (const float*)d_in[0];
    const float* W1 = (const float*)d_in[1];
    const float* b1 = (const float*)d_in[2];
    const float* W2 = (const float*)d_in[3];
    const float* b2 = (const float*)d_in[4];
    float* out = (float*)d_out;

    cudaFuncSetAttribute(knn_kernel, cudaFuncAttributeMaxDynamicSharedMemorySize,
                         (int)KNN_SMEM_BYTES);

    pq_kernel<<<NN / 8, 256>>>(x, W1, b1);
    knn_kernel<<<dim3(NN / TI, SEG), 128, KNN_SMEM_BYTES>>>(x);
    agg_kernel<<<NN, 128>>>(W2, b2, out);
}